// round 7
// baseline (speedup 1.0000x reference)
#include <cuda_runtime.h>
#include <cuda_fp16.h>

// ---------------------------------------------------------------------------
// ISTFT: B=16, NFREQ=513, T=2048, NFFT=1024, HOP=256, WIN=1024, PAD=384
// Pass 1: real-packed 512-pt radix-8 Stockham inverse FFT.
//         Hermitian packing fed by dual global loads (L1 absorbs the mirror),
//         register-fused stages, single in-place smem buffer, fp16 frame store.
// Pass 2: overlap-add from fp16 frames; interior env == 1.5 (Hann, hop=N/4),
//         8-deep load pipelining.
// ---------------------------------------------------------------------------

#define BATCH     16
#define NFREQ     513
#define TT        2048
#define NFFT      1024
#define HOP       256
#define PAD       384
#define OUT_PER_B 524288                 // (T-1)*HOP + WIN - 2*PAD = 1<<19
#define NFRAMES   (BATCH * TT)           // 32768
#define FPB       8                      // frames per block (pass 1)

#define SM_FLOATS (8192 + 2048)          // data (in-place) + twiddle tables
#define SM_BYTES  (SM_FLOATS * 4)        // 40960 bytes

__device__ __half g_frames[(size_t)NFRAMES * NFFT];   // 64 MiB scratch (fp16)

// conflict-free shared index: phi(pos) = pos ^ (pos>>3); idx = phi*8 + f
__device__ __forceinline__ int sidx(int pos, int f) {
    return ((pos ^ (pos >> 3)) << 3) | f;
}

// radix-8 butterfly on 8 complex registers (inverse FFT, +i convention)
__device__ __forceinline__ void bfly8(const float* xr, const float* xi,
                                      float* Xr, float* Xi)
{
    float e0r = xr[0] + xr[4], e0i = xi[0] + xi[4];
    float e1r = xr[0] - xr[4], e1i = xi[0] - xi[4];
    float e2r = xr[2] + xr[6], e2i = xi[2] + xi[6];
    float e3r = xr[2] - xr[6], e3i = xi[2] - xi[6];
    float E0r = e0r + e2r, E0i = e0i + e2i;
    float E2r = e0r - e2r, E2i = e0i - e2i;
    float E1r = e1r - e3i, E1i = e1i + e3r;
    float E3r = e1r + e3i, E3i = e1i - e3r;

    float o0r = xr[1] + xr[5], o0i = xi[1] + xi[5];
    float o1r = xr[1] - xr[5], o1i = xi[1] - xi[5];
    float o2r = xr[3] + xr[7], o2i = xi[3] + xi[7];
    float o3r = xr[3] - xr[7], o3i = xi[3] - xi[7];
    float O0r = o0r + o2r, O0i = o0i + o2i;
    float O2r = o0r - o2r, O2i = o0i - o2i;
    float O1r = o1r - o3i, O1i = o1i + o3r;
    float O3r = o1r + o3i, O3i = o1i - o3r;

    const float RS = 0.70710678118654752440f;
    float c1r = RS * (O1r - O1i), c1i = RS * (O1r + O1i);   // e^{+i pi/4} O1
    float c2r = -O2i,             c2i = O2r;                // i * O2
    float c3r = -RS * (O3r + O3i), c3i = RS * (O3r - O3i);  // e^{+3i pi/4} O3

    Xr[0] = E0r + O0r; Xi[0] = E0i + O0i;
    Xr[4] = E0r - O0r; Xi[4] = E0i - O0i;
    Xr[1] = E1r + c1r; Xi[1] = E1i + c1i;
    Xr[5] = E1r - c1r; Xi[5] = E1i - c1i;
    Xr[2] = E2r + c2r; Xi[2] = E2i + c2i;
    Xr[6] = E2r - c2r; Xi[6] = E2i - c2i;
    Xr[3] = E3r + c3r; Xi[3] = E3i + c3i;
    Xr[7] = E3r - c3r; Xi[7] = E3i - c3i;
}

__global__ void __launch_bounds__(512)
istft_fft_kernel(const float* __restrict__ spr,
                 const float* __restrict__ spi,
                 const float* __restrict__ win)
{
    extern __shared__ float sm[];
    float* Ar  = sm;            // 4096
    float* Ai  = sm + 4096;     // 4096
    float* xb  = sm;            // output staging overlays A (8192 floats)
    float* twr = sm + 8192;     // e^{+2pi i j/512}, j<512
    float* twi = twr + 512;
    float* ztr = twi + 512;     // e^{+2pi i k/1024}, k<512
    float* zti = ztr + 512;

    const int tid = threadIdx.x;
    const int f   = tid & 7;    // frame lane
    const int w   = tid >> 3;   // worker 0..63

    {
        float s, c;
        sincospif((float)tid * (1.0f / 256.0f), &s, &c);
        twr[tid] = c; twi[tid] = s;
        sincospif((float)tid * (1.0f / 512.0f), &s, &c);
        ztr[tid] = c; zti[tid] = s;
    }
    __syncthreads();            // tables ready (no data staging round-trip)

    const int fr0 = blockIdx.x * FPB;
    const int b   = fr0 >> 11;
    const int t0  = fr0 & 2047;
    const float* pr  = spr + (size_t)b * NFREQ * TT + (t0 + f);
    const float* pim = spi + (size_t)b * NFREQ * TT + (t0 + f);

    float vr[8], vi[8];

    // ---- Hermitian packing Z[k]=E+iO from dual global loads (k = w+64m) ----
    // Partner X[512-k] is read by its mirror thread too -> L1 hit, no extra DRAM.
    #pragma unroll
    for (int m = 0; m < 8; m++) {
        int k  = w + (m << 6);
        int kc = 512 - k;                       // 512..1 (row 512 exists)
        float xkr = __ldg(pr  + k  * TT);
        float xki = __ldg(pim + k  * TT);
        float xcr = __ldg(pr  + kc * TT);
        float xci = __ldg(pim + kc * TT);
        if (k == 0) { xki = 0.0f; xci = 0.0f; } // irfft ignores Im at DC/Nyquist
        float Er = 0.5f * (xkr + xcr);
        float Ei = 0.5f * (xki - xci);
        float Dr = 0.5f * (xkr - xcr);
        float Di = 0.5f * (xki + xci);
        float ct = ztr[k], st = zti[k];
        float Or = fmaf(ct, Dr, -st * Di);
        float Oi = fmaf(ct, Di,  st * Dr);
        vr[m] = Er - Oi;
        vi[m] = Ei + Or;
    }

    // ---- stage 1 (S=1): registers -> A, twiddle w^{m*w} ----
    {
        float Xr[8], Xi[8];
        bfly8(vr, vi, Xr, Xi);
        #pragma unroll
        for (int m = 0; m < 8; m++) {
            float r = Xr[m], i = Xi[m];
            if (m > 0) {
                float cr = twr[m * w], ci = twi[m * w];
                float nr = fmaf(r, cr, -i * ci);
                float ni = fmaf(r, ci,  i * cr);
                r = nr; i = ni;
            }
            int p = sidx(8 * w + m, f);
            Ar[p] = r; Ai[p] = i;
        }
    }
    __syncthreads();

    // ---- stage 2 (S=8): A -> regs -> A, twiddle w^{m*ps}, ps = 8*(w>>3) ----
    {
        #pragma unroll
        for (int j = 0; j < 8; j++) {
            int p = sidx(w + (j << 6), f);
            vr[j] = Ar[p]; vi[j] = Ai[p];
        }
        __syncthreads();   // reads done -> safe to overwrite in place
        float Xr[8], Xi[8];
        bfly8(vr, vi, Xr, Xi);
        const int q  = w & 7;
        const int ps = w - q;
        const int wb = q + 8 * ps;
        #pragma unroll
        for (int m = 0; m < 8; m++) {
            float r = Xr[m], i = Xi[m];
            if (m > 0) {
                float cr = twr[m * ps], ci = twi[m * ps];
                float nr = fmaf(r, cr, -i * ci);
                float ni = fmaf(r, ci,  i * cr);
                r = nr; i = ni;
            }
            int p = sidx(wb + 8 * m, f);
            Ar[p] = r; Ai[p] = i;
        }
    }
    __syncthreads();

    // ---- stage 3 (S=64, no twiddle): A -> regs; stage output into xb ----
    #pragma unroll
    for (int j = 0; j < 8; j++) {
        int p = sidx(w + (j << 6), f);
        vr[j] = Ar[p]; vi[j] = Ai[p];
    }
    __syncthreads();   // reads done -> xb may overwrite A
    {
        float Xr[8], Xi[8];
        bfly8(vr, vi, Xr, Xi);

        // unpack x[2n]=Re z, x[2n+1]=Im z; window + scale; stage into xb
        const float2* w2 = (const float2*)win;
        const float inv = 1.0f / 512.0f;
        #pragma unroll
        for (int m = 0; m < 8; m++) {
            int n = w + (m << 6);
            float2 wv = __ldg(w2 + n);
            xb[sidx(2 * n,     f)] = Xr[m] * inv * wv.x;
            xb[sidx(2 * n + 1, f)] = Xi[m] * inv * wv.y;
        }
    }
    __syncthreads();

    // ---- coalesced fp16 output: warp writes 4 frames x 64B contiguous ----
    {
        const int W    = tid >> 5;
        const int lane = tid & 31;
        const int g    = lane >> 3;
        const int e    = lane & 7;
        const int f3   = ((W & 1) << 2) + g;          // frame 0..7
        const int u0   = ((W >> 1) << 3) + e;         // chunk 0..63
        __half* gout = g_frames + (size_t)(fr0 + f3) * NFFT;
        #pragma unroll
        for (int j = 0; j < 4; j++) {
            int pos = (u0 + (j << 6)) << 2;           // 0..1020, step 4
            __half2 h0 = __floats2half2_rn(xb[sidx(pos,     f3)],
                                           xb[sidx(pos + 1, f3)]);
            __half2 h1 = __floats2half2_rn(xb[sidx(pos + 2, f3)],
                                           xb[sidx(pos + 3, f3)]);
            uint2 u;
            u.x = *(unsigned*)&h0;
            u.y = *(unsigned*)&h1;
            *(uint2*)(gout + pos) = u;
        }
    }
}

__device__ __forceinline__ float4 h4f(uint2 u) {
    __half2 h0 = *(__half2*)&u.x;
    __half2 h1 = *(__half2*)&u.y;
    float2 f0 = __half22float2(h0);
    float2 f1 = __half22float2(h1);
    return make_float4(f0.x, f0.y, f1.x, f1.y);
}

// Pass 2: interior samples use Hann/hop=N/4 identity: sum_j w^2(x+256j) = 1.5
__global__ void __launch_bounds__(256)
istft_ola_kernel(const float* __restrict__ win, float* __restrict__ out)
{
    const unsigned tid = blockIdx.x * 256u + threadIdx.x;

    const unsigned g0 = tid;
    const unsigned g1 = tid + 1048576u;
    const unsigned base0 = g0 << 2;
    const unsigned base1 = g1 << 2;
    const int b0 = base0 >> 19, o0 = base0 & (OUT_PER_B - 1);
    const int b1 = base1 >> 19, o1 = base1 & (OUT_PER_B - 1);
    const int l0 = o0 + PAD,    l1 = o1 + PAD;
    const bool in0 = (o0 >= 640 && o0 < 523904);
    const bool in1 = (o1 >= 640 && o1 < 523904);

    if (in0 && in1) {
        // fast path: 8 independent loads in flight before any math
        const __half* a0 = g_frames + (size_t)b0 * TT * NFFT + l0 + 768 * ((l0 >> 8) - 3);
        const __half* a1 = g_frames + (size_t)b1 * TT * NFFT + l1 + 768 * ((l1 >> 8) - 3);
        uint2 u0 = __ldg((const uint2*)(a0));
        uint2 u1 = __ldg((const uint2*)(a0 + 768));
        uint2 u2 = __ldg((const uint2*)(a0 + 1536));
        uint2 u3 = __ldg((const uint2*)(a0 + 2304));
        uint2 u4 = __ldg((const uint2*)(a1));
        uint2 u5 = __ldg((const uint2*)(a1 + 768));
        uint2 u6 = __ldg((const uint2*)(a1 + 1536));
        uint2 u7 = __ldg((const uint2*)(a1 + 2304));
        float4 v0 = h4f(u0), v1 = h4f(u1), v2 = h4f(u2), v3 = h4f(u3);
        float4 w0 = h4f(u4), w1 = h4f(u5), w2 = h4f(u6), w3 = h4f(u7);
        float4 r0, r1;
        r0.x = (v0.x + v1.x + v2.x + v3.x) * (2.0f / 3.0f);
        r0.y = (v0.y + v1.y + v2.y + v3.y) * (2.0f / 3.0f);
        r0.z = (v0.z + v1.z + v2.z + v3.z) * (2.0f / 3.0f);
        r0.w = (v0.w + v1.w + v2.w + v3.w) * (2.0f / 3.0f);
        r1.x = (w0.x + w1.x + w2.x + w3.x) * (2.0f / 3.0f);
        r1.y = (w0.y + w1.y + w2.y + w3.y) * (2.0f / 3.0f);
        r1.z = (w0.z + w1.z + w2.z + w3.z) * (2.0f / 3.0f);
        r1.w = (w0.w + w1.w + w2.w + w3.w) * (2.0f / 3.0f);
        *(float4*)(out + base0) = r0;
        *(float4*)(out + base1) = r1;
        return;
    }

    // slow path: per-sample variable frame count + env (edges only)
    #pragma unroll
    for (int h = 0; h < 2; h++) {
        const int b = h ? b1 : b0;
        const int o = h ? o1 : o0;
        const unsigned base = h ? base1 : base0;
        const int l = o + PAD;
        const __half* gb = g_frames + (size_t)b * TT * NFFT;

        if (o >= 640 && o < 523904) {
            const int tmax = l >> 8;
            const __half* a = gb + l + 768 * (tmax - 3);
            float4 v0 = h4f(__ldg((const uint2*)(a)));
            float4 v1 = h4f(__ldg((const uint2*)(a + 768)));
            float4 v2 = h4f(__ldg((const uint2*)(a + 1536)));
            float4 v3 = h4f(__ldg((const uint2*)(a + 2304)));
            float4 r;
            r.x = (v0.x + v1.x + v2.x + v3.x) * (2.0f / 3.0f);
            r.y = (v0.y + v1.y + v2.y + v3.y) * (2.0f / 3.0f);
            r.z = (v0.z + v1.z + v2.z + v3.z) * (2.0f / 3.0f);
            r.w = (v0.w + v1.w + v2.w + v3.w) * (2.0f / 3.0f);
            *(float4*)(out + base) = r;
        } else {
            #pragma unroll
            for (int s = 0; s < 4; s++) {
                int ls = l + s;
                int tmax = ls >> 8;           if (tmax > TT - 1) tmax = TT - 1;
                int tmin = (ls >= 1023) ? ((ls - 768) >> 8) : 0;
                float acc = 0.0f, env = 0.0f;
                for (int t = tmin; t <= tmax; t++) {
                    int off = ls - (t << 8);
                    float wv = __ldg(win + off);
                    env = fmaf(wv, wv, env);
                    acc += __half2float(__ldg(gb + (size_t)t * NFFT + off));
                }
                out[base + s] = acc / env;
            }
        }
    }
}

extern "C" void kernel_launch(void* const* d_in, const int* in_sizes, int n_in,
                              void* d_out, int out_size)
{
    const float* spr = (const float*)d_in[0];
    const float* spi = (const float*)d_in[1];
    const float* win = (const float*)d_in[2];
    float* out = (float*)d_out;

    cudaFuncSetAttribute(istft_fft_kernel,
                         cudaFuncAttributeMaxDynamicSharedMemorySize, SM_BYTES);

    istft_fft_kernel<<<NFRAMES / FPB, 512, SM_BYTES>>>(spr, spi, win);

    istft_ola_kernel<<<4096, 256>>>(win, out);
}

// round 8
// speedup vs baseline: 1.1582x; 1.1582x over previous
#include <cuda_runtime.h>

// ---------------------------------------------------------------------------
// ISTFT fused: B=16, NFREQ=513, T=2048, NFFT=1024, HOP=256, WIN=1024, PAD=384
// Kernel A: zero the atomic stripes of out (tmax mod 8 in {0,1,2}).
// Kernel B: per block: 8 frames real-packed 512-pt radix-8 Stockham inverse
//           FFT -> windowed frames in shared -> overlap-add directly to out
//           (plain stores for in-block samples, 2-way atomicAdd on stripes,
//           explicit env at batch edges). No global scratch at all.
// ---------------------------------------------------------------------------

#define BATCH     16
#define NFREQ     513
#define TT        2048
#define NFFT      1024
#define HOP       256
#define PAD       384
#define OUT_PER_B 524288                 // (T-1)*HOP + WIN - 2*PAD = 1<<19
#define NFRAMES   (BATCH * TT)           // 32768
#define FPB       8                      // frames per block
#define YPITCH    1032                   // frame pitch in shared (pad 8)

#define SM_FLOATS (2048 + 8256)          // tables + (A overlay y)
#define SM_BYTES  (SM_FLOATS * 4)        // 41216 bytes

// conflict-free shared index for FFT stages: phi(pos) = pos ^ (pos>>3)
__device__ __forceinline__ int sidx(int pos, int f) {
    return ((pos ^ (pos >> 3)) << 3) | f;
}

// radix-8 butterfly on 8 complex registers (inverse FFT, +i convention)
__device__ __forceinline__ void bfly8(const float* xr, const float* xi,
                                      float* Xr, float* Xi)
{
    float e0r = xr[0] + xr[4], e0i = xi[0] + xi[4];
    float e1r = xr[0] - xr[4], e1i = xi[0] - xi[4];
    float e2r = xr[2] + xr[6], e2i = xi[2] + xi[6];
    float e3r = xr[2] - xr[6], e3i = xi[2] - xi[6];
    float E0r = e0r + e2r, E0i = e0i + e2i;
    float E2r = e0r - e2r, E2i = e0i - e2i;
    float E1r = e1r - e3i, E1i = e1i + e3r;
    float E3r = e1r + e3i, E3i = e1i - e3r;

    float o0r = xr[1] + xr[5], o0i = xi[1] + xi[5];
    float o1r = xr[1] - xr[5], o1i = xi[1] - xi[5];
    float o2r = xr[3] + xr[7], o2i = xi[3] + xi[7];
    float o3r = xr[3] - xr[7], o3i = xi[3] - xi[7];
    float O0r = o0r + o2r, O0i = o0i + o2i;
    float O2r = o0r - o2r, O2i = o0i - o2i;
    float O1r = o1r - o3i, O1i = o1i + o3r;
    float O3r = o1r + o3i, O3i = o1i - o3r;

    const float RS = 0.70710678118654752440f;
    float c1r = RS * (O1r - O1i), c1i = RS * (O1r + O1i);   // e^{+i pi/4} O1
    float c2r = -O2i,             c2i = O2r;                // i * O2
    float c3r = -RS * (O3r + O3i), c3i = RS * (O3r - O3i);  // e^{+3i pi/4} O3

    Xr[0] = E0r + O0r; Xi[0] = E0i + O0i;
    Xr[4] = E0r - O0r; Xi[4] = E0i - O0i;
    Xr[1] = E1r + c1r; Xi[1] = E1i + c1i;
    Xr[5] = E1r - c1r; Xi[5] = E1i - c1i;
    Xr[2] = E2r + c2r; Xi[2] = E2i + c2i;
    Xr[6] = E2r - c2r; Xi[6] = E2i - c2i;
    Xr[3] = E3r + c3r; Xi[3] = E3i + c3i;
    Xr[7] = E3r - c3r; Xi[7] = E3i - c3i;
}

// zero the stripe samples ((o+PAD)>>8 mod 8 < 3) that receive atomicAdds
__global__ void __launch_bounds__(256)
istft_zero_kernel(float4* __restrict__ out4)
{
    unsigned t = blockIdx.x * 256u + threadIdx.x;      // < 2097152
    unsigned o = (t << 2) & (OUT_PER_B - 1);
    if ((((o + PAD) >> 8) & 7u) < 3u)
        out4[t] = make_float4(0.f, 0.f, 0.f, 0.f);
}

__global__ void __launch_bounds__(512)
istft_fused_kernel(const float* __restrict__ spr,
                   const float* __restrict__ spi,
                   const float* __restrict__ win,
                   float* __restrict__ out)
{
    extern __shared__ float sm[];
    float* twr = sm;            // e^{+2pi i j/512}, j<512
    float* twi = sm + 512;
    float* ztr = sm + 1024;     // e^{+2pi i k/1024}, k<512
    float* zti = sm + 1536;
    float* Ar  = sm + 2048;     // 4096
    float* Ai  = sm + 6144;     // 4096
    float* y   = sm + 2048;     // frame staging overlays A: 8*YPITCH = 8256

    const int tid = threadIdx.x;
    const int f   = tid & 7;    // frame lane
    const int w   = tid >> 3;   // worker 0..63

    {
        float s, c;
        sincospif((float)tid * (1.0f / 256.0f), &s, &c);
        twr[tid] = c; twi[tid] = s;
        sincospif((float)tid * (1.0f / 512.0f), &s, &c);
        ztr[tid] = c; zti[tid] = s;
    }

    const int fr0 = blockIdx.x * FPB;
    const int b   = fr0 >> 11;
    const int t0  = fr0 & 2047;
    const float* pr  = spr + (size_t)b * NFREQ * TT + (t0 + f);
    const float* pim = spi + (size_t)b * NFREQ * TT + (t0 + f);

    // ---- load X[0..511] into A; X[512] in register on w==0 threads ----
    #pragma unroll
    for (int m = 0; m < 8; m++) {
        int k = w + (m << 6);
        float re = __ldg(pr  + k * TT);
        float im = __ldg(pim + k * TT);
        if (k == 0) im = 0.0f;
        Ar[sidx(k, f)] = re;
        Ai[sidx(k, f)] = im;
    }
    float x512r = 0.0f;
    if (w == 0) x512r = __ldg(pr + 512 * TT);
    __syncthreads();

    float vr[8], vi[8];

    // ---- Hermitian packing Z[k]=E+iO (k = w+64m) into registers ----
    #pragma unroll
    for (int m = 0; m < 8; m++) {
        int k = w + (m << 6);
        float xkr = Ar[sidx(k, f)], xki = Ai[sidx(k, f)];
        float xcr, xci;
        if (k == 0) { xcr = x512r; xci = 0.0f; }
        else        { int k2 = 512 - k; xcr = Ar[sidx(k2, f)]; xci = Ai[sidx(k2, f)]; }
        float Er = 0.5f * (xkr + xcr);
        float Ei = 0.5f * (xki - xci);
        float Dr = 0.5f * (xkr - xcr);
        float Di = 0.5f * (xki + xci);
        float ct = ztr[k], st = zti[k];
        float Or = fmaf(ct, Dr, -st * Di);
        float Oi = fmaf(ct, Di,  st * Dr);
        vr[m] = Er - Oi;
        vi[m] = Ei + Or;
    }
    __syncthreads();   // packing reads done -> safe to overwrite A

    // ---- stage 1 (S=1): regs -> A, twiddle w^{m*w} ----
    {
        float Xr[8], Xi[8];
        bfly8(vr, vi, Xr, Xi);
        #pragma unroll
        for (int m = 0; m < 8; m++) {
            float r = Xr[m], i = Xi[m];
            if (m > 0) {
                float cr = twr[m * w], ci = twi[m * w];
                float nr = fmaf(r, cr, -i * ci);
                float ni = fmaf(r, ci,  i * cr);
                r = nr; i = ni;
            }
            int p = sidx(8 * w + m, f);
            Ar[p] = r; Ai[p] = i;
        }
    }
    __syncthreads();

    // ---- stage 2 (S=8): A -> regs -> A, twiddle w^{m*ps}, ps = 8*(w>>3) ----
    {
        #pragma unroll
        for (int j = 0; j < 8; j++) {
            int p = sidx(w + (j << 6), f);
            vr[j] = Ar[p]; vi[j] = Ai[p];
        }
        __syncthreads();
        float Xr[8], Xi[8];
        bfly8(vr, vi, Xr, Xi);
        const int q  = w & 7;
        const int ps = w - q;
        const int wb = q + 8 * ps;
        #pragma unroll
        for (int m = 0; m < 8; m++) {
            float r = Xr[m], i = Xi[m];
            if (m > 0) {
                float cr = twr[m * ps], ci = twi[m * ps];
                float nr = fmaf(r, cr, -i * ci);
                float ni = fmaf(r, ci,  i * cr);
                r = nr; i = ni;
            }
            int p = sidx(wb + 8 * m, f);
            Ar[p] = r; Ai[p] = i;
        }
    }
    __syncthreads();

    // ---- stage 3 (S=64): A -> regs; windowed frames -> y[f][pos] ----
    #pragma unroll
    for (int j = 0; j < 8; j++) {
        int p = sidx(w + (j << 6), f);
        vr[j] = Ar[p]; vi[j] = Ai[p];
    }
    __syncthreads();   // reads done -> y may overwrite A
    {
        float Xr[8], Xi[8];
        bfly8(vr, vi, Xr, Xi);
        const float2* w2 = (const float2*)win;
        const float inv = 1.0f / 512.0f;
        float* yf = y + f * YPITCH;
        #pragma unroll
        for (int m = 0; m < 8; m++) {
            int n = w + (m << 6);
            float2 wv = __ldg(w2 + n);
            float2 o;
            o.x = Xr[m] * inv * wv.x;
            o.y = Xi[m] * inv * wv.y;
            *(float2*)(yf + 2 * n) = o;        // pos 2n, 2n+1
        }
    }
    __syncthreads();

    // =================== overlap-add from shared ===================
    float* outb = out + (size_t)b * OUT_PER_B;
    const float TW3 = 2.0f / 3.0f;

    // interior-owned: tmax in [t0+3, t0+7], l in [256(t0+3), 256(t0+8))
    #pragma unroll
    for (int s = tid; s < 1280; s += 512) {
        int l   = ((t0 + 3) << 8) + s;
        int fl  = 3 + (s >> 8);            // tmax - t0, 3..7
        int pos = s & 255;
        float acc = y[(fl - 3) * YPITCH + pos + 768]
                  + y[(fl - 2) * YPITCH + pos + 512]
                  + y[(fl - 1) * YPITCH + pos + 256]
                  + y[(fl    ) * YPITCH + pos      ];
        outb[l - PAD] = acc * TW3;
    }

    if (t0 != 0) {
        // bottom stripe: l in [256 t0, 256(t0+3)), this block adds frames t0..tmax
        #pragma unroll
        for (int s = tid; s < 768; s += 512) {
            int r = s >> 8;                // tmax - t0: 0,1,2
            float acc = y[s];              // j=0, pos = s
            if (r >= 1) acc += y[1 * YPITCH + s - 256];
            if (r >= 2) acc += y[2 * YPITCH + s - 512];
            int l = (t0 << 8) + s;
            atomicAdd(outb + (l - PAD), acc * TW3);
        }
    } else {
        // batch start: l in [384, 768), all contributors in-block, env varies
        if (tid < 384) {
            int l = PAD + tid;
            int tmax = l >> 8;             // 1 or 2
            float acc = 0.0f, env = 0.0f;
            for (int t = 0; t <= tmax; t++) {
                int pos = l - (t << 8);
                float wv = __ldg(win + pos);
                env = fmaf(wv, wv, env);
                acc += y[t * YPITCH + pos];
            }
            outb[l - PAD] = acc / env;
        }
    }

    if (t0 != 2040) {
        // top stripe: l in [256(t0+8), 256(t0+11)), adds frames tmax-3..t0+7
        #pragma unroll
        for (int s = tid; s < 768; s += 512) {
            int r = s >> 8;                // 0,1,2 ; count = 3 - r
            float acc = y[7 * YPITCH + s + 256];
            if (r <= 1) acc += y[6 * YPITCH + s + 512];
            if (r == 0) acc += y[5 * YPITCH + s + 768];
            int l = ((t0 + 8) << 8) + s;
            atomicAdd(outb + (l - PAD), acc * TW3);
        }
    } else {
        // batch end: l in [524288, 524672), all contributors in-block
        if (tid < 384) {
            int l = 524288 + tid;
            int tmin = (l - 768) >> 8;     // 2045..2046
            float acc = 0.0f, env = 0.0f;
            for (int t = tmin; t <= 2047; t++) {
                int pos = l - (t << 8);
                float wv = __ldg(win + pos);
                env = fmaf(wv, wv, env);
                acc += y[(t - 2040) * YPITCH + pos];
            }
            outb[l - PAD] = acc / env;
        }
    }
}

extern "C" void kernel_launch(void* const* d_in, const int* in_sizes, int n_in,
                              void* d_out, int out_size)
{
    const float* spr = (const float*)d_in[0];
    const float* spi = (const float*)d_in[1];
    const float* win = (const float*)d_in[2];
    float* out = (float*)d_out;

    cudaFuncSetAttribute(istft_fused_kernel,
                         cudaFuncAttributeMaxDynamicSharedMemorySize, SM_BYTES);

    istft_zero_kernel<<<8192, 256>>>((float4*)out);
    istft_fused_kernel<<<NFRAMES / FPB, 512, SM_BYTES>>>(spr, spi, win, out);
}

// round 9
// speedup vs baseline: 1.4073x; 1.2151x over previous
#include <cuda_runtime.h>

// ---------------------------------------------------------------------------
// ISTFT fused: B=16, NFREQ=513, T=2048, NFFT=1024, HOP=256, WIN=1024, PAD=384
// Kernel A: zero the atomic stripes of out (tmax mod 8 in {0,1,2}).
// Kernel B: 8 frames/block, real-packed 512-pt radix-8 Stockham inverse FFT
//           with float2-interleaved shared (LDS.64/STS.64, conflict-free
//           swizzle) and register-computed twiddles; windowed frames staged
//           in shared; overlap-add direct to out (stores interior, 2-way
//           atomicAdd stripes, explicit env at batch edges). No global scratch.
// ---------------------------------------------------------------------------

#define BATCH     16
#define NFREQ     513
#define TT        2048
#define NFFT      1024
#define HOP       256
#define PAD       384
#define OUT_PER_B 524288                 // (T-1)*HOP + WIN - 2*PAD = 1<<19
#define NFRAMES   (BATCH * TT)           // 32768
#define FPB       8                      // frames per block
#define YPITCH    1028                   // 1028 % 32 == 4 -> bank-perm rows

#define SM_FLOATS (FPB * YPITCH + 8)     // max(A: 8192, y: 8224)
#define SM_BYTES  (SM_FLOATS * 4)        // 32928 bytes

// conflict-free shared index (float2 units): phi(pos) = pos ^ (pos>>3)
__device__ __forceinline__ int sidx(int pos, int f) {
    return ((pos ^ (pos >> 3)) << 3) | f;
}

// radix-8 butterfly on 8 complex registers (inverse FFT, +i convention)
__device__ __forceinline__ void bfly8(const float* xr, const float* xi,
                                      float* Xr, float* Xi)
{
    float e0r = xr[0] + xr[4], e0i = xi[0] + xi[4];
    float e1r = xr[0] - xr[4], e1i = xi[0] - xi[4];
    float e2r = xr[2] + xr[6], e2i = xi[2] + xi[6];
    float e3r = xr[2] - xr[6], e3i = xi[2] - xi[6];
    float E0r = e0r + e2r, E0i = e0i + e2i;
    float E2r = e0r - e2r, E2i = e0i - e2i;
    float E1r = e1r - e3i, E1i = e1i + e3r;
    float E3r = e1r + e3i, E3i = e1i - e3r;

    float o0r = xr[1] + xr[5], o0i = xi[1] + xi[5];
    float o1r = xr[1] - xr[5], o1i = xi[1] - xi[5];
    float o2r = xr[3] + xr[7], o2i = xi[3] + xi[7];
    float o3r = xr[3] - xr[7], o3i = xi[3] - xi[7];
    float O0r = o0r + o2r, O0i = o0i + o2i;
    float O2r = o0r - o2r, O2i = o0i - o2i;
    float O1r = o1r - o3i, O1i = o1i + o3r;
    float O3r = o1r + o3i, O3i = o1i - o3r;

    const float RS = 0.70710678118654752440f;
    float c1r = RS * (O1r - O1i), c1i = RS * (O1r + O1i);   // e^{+i pi/4} O1
    float c2r = -O2i,             c2i = O2r;                // i * O2
    float c3r = -RS * (O3r + O3i), c3i = RS * (O3r - O3i);  // e^{+3i pi/4} O3

    Xr[0] = E0r + O0r; Xi[0] = E0i + O0i;
    Xr[4] = E0r - O0r; Xi[4] = E0i - O0i;
    Xr[1] = E1r + c1r; Xi[1] = E1i + c1i;
    Xr[5] = E1r - c1r; Xi[5] = E1i - c1i;
    Xr[2] = E2r + c2r; Xi[2] = E2i + c2i;
    Xr[6] = E2r - c2r; Xi[6] = E2i - c2i;
    Xr[3] = E3r + c3r; Xi[3] = E3i + c3i;
    Xr[7] = E3r - c3r; Xi[7] = E3i - c3i;
}

// zero the stripe samples ((o+PAD)>>8 mod 8 < 3) that receive atomicAdds
__global__ void __launch_bounds__(256)
istft_zero_kernel(float4* __restrict__ out4)
{
    unsigned t = blockIdx.x * 256u + threadIdx.x;      // < 2097152
    unsigned o = (t << 2) & (OUT_PER_B - 1);
    if ((((o + PAD) >> 8) & 7u) < 3u)
        out4[t] = make_float4(0.f, 0.f, 0.f, 0.f);
}

__global__ void __launch_bounds__(512)
istft_fused_kernel(const float* __restrict__ spr,
                   const float* __restrict__ spi,
                   const float* __restrict__ win,
                   float* __restrict__ out)
{
    extern __shared__ float sm[];
    float2* A = (float2*)sm;    // 4096 float2 (FFT work buffer)
    float*  y = sm;             // frame staging overlays A: 8*YPITCH floats

    const int tid = threadIdx.x;
    const int f   = tid & 7;    // frame lane
    const int w   = tid >> 3;   // worker 0..63

    // register twiddle bases
    float zwr, zwi;   // e^{+2pi i w/1024}
    __sincosf((float)w * 6.1359231515e-3f, &zwi, &zwr);
    float w1r = fmaf(zwr, zwr, -zwi * zwi);   // e^{+2pi i w/512} = zw^2
    float w1i = 2.0f * zwr * zwi;
    const int h = w >> 3;
    float bhr, bhi;   // e^{+2pi i h/64}
    __sincosf((float)h * 9.8174770424e-2f, &bhi, &bhr);

    const int fr0 = blockIdx.x * FPB;
    const int b   = fr0 >> 11;
    const int t0  = fr0 & 2047;
    const float* pr  = spr + (size_t)b * NFREQ * TT + (t0 + f);
    const float* pim = spi + (size_t)b * NFREQ * TT + (t0 + f);

    // ---- load X[0..511] into A; X[512] in register on w==0 threads ----
    #pragma unroll
    for (int m = 0; m < 8; m++) {
        int k = w + (m << 6);
        float re = __ldg(pr  + k * TT);
        float im = __ldg(pim + k * TT);
        if (k == 0) im = 0.0f;
        A[sidx(k, f)] = make_float2(re, im);
    }
    float x512r = 0.0f;
    if (w == 0) x512r = __ldg(pr + 512 * TT);
    __syncthreads();

    float vr[8], vi[8];

    // ---- Hermitian packing Z[k]=E+iO (k = w+64m); twiddle chain from zw ----
    {
        const float S16r = 0.92387953251128675613f;  // e^{+2pi i/16}
        const float S16i = 0.38268343236508977173f;
        float ct = zwr, st = zwi;
        #pragma unroll
        for (int m = 0; m < 8; m++) {
            int k = w + (m << 6);
            float2 zk = A[sidx(k, f)];
            float xcr, xci;
            if (k == 0) { xcr = x512r; xci = 0.0f; }
            else        { float2 zc = A[sidx(512 - k, f)]; xcr = zc.x; xci = zc.y; }
            float Er = 0.5f * (zk.x + xcr);
            float Ei = 0.5f * (zk.y - xci);
            float Dr = 0.5f * (zk.x - xcr);
            float Di = 0.5f * (zk.y + xci);
            float Or = fmaf(ct, Dr, -st * Di);
            float Oi = fmaf(ct, Di,  st * Dr);
            vr[m] = Er - Oi;
            vi[m] = Ei + Or;
            float nc = fmaf(ct, S16r, -st * S16i);   // rotate by e^{2pi i/16}
            float ns = fmaf(ct, S16i,  st * S16r);
            ct = nc; st = ns;
        }
    }
    __syncthreads();   // packing reads done -> safe to overwrite A

    // ---- stage 1 (S=1): regs -> A, twiddle w1^m ----
    {
        float Xr[8], Xi[8];
        bfly8(vr, vi, Xr, Xi);
        A[sidx(8 * w, f)] = make_float2(Xr[0], Xi[0]);
        float cr = w1r, ci = w1i;
        #pragma unroll
        for (int m = 1; m < 8; m++) {
            A[sidx(8 * w + m, f)] =
                make_float2(fmaf(Xr[m], cr, -Xi[m] * ci),
                            fmaf(Xr[m], ci,  Xi[m] * cr));
            float nc = fmaf(cr, w1r, -ci * w1i);
            float ns = fmaf(cr, w1i,  ci * w1r);
            cr = nc; ci = ns;
        }
    }
    __syncthreads();

    // ---- stage 2 (S=8): A -> regs -> A, twiddle bh^m ----
    {
        #pragma unroll
        for (int j = 0; j < 8; j++) {
            float2 z = A[sidx(w + (j << 6), f)];
            vr[j] = z.x; vi[j] = z.y;
        }
        __syncthreads();
        float Xr[8], Xi[8];
        bfly8(vr, vi, Xr, Xi);
        const int q  = w & 7;
        const int wb = q + 64 * h;         // q + 8*ps, ps = 8h
        A[sidx(wb, f)] = make_float2(Xr[0], Xi[0]);
        float cr = bhr, ci = bhi;
        #pragma unroll
        for (int m = 1; m < 8; m++) {
            A[sidx(wb + 8 * m, f)] =
                make_float2(fmaf(Xr[m], cr, -Xi[m] * ci),
                            fmaf(Xr[m], ci,  Xi[m] * cr));
            float nc = fmaf(cr, bhr, -ci * bhi);
            float ns = fmaf(cr, bhi,  ci * bhr);
            cr = nc; ci = ns;
        }
    }
    __syncthreads();

    // ---- stage 3 (S=64): A -> regs; windowed frames -> y[f][pos] ----
    #pragma unroll
    for (int j = 0; j < 8; j++) {
        float2 z = A[sidx(w + (j << 6), f)];
        vr[j] = z.x; vi[j] = z.y;
    }
    __syncthreads();   // reads done -> y may overwrite A
    {
        float Xr[8], Xi[8];
        bfly8(vr, vi, Xr, Xi);
        const float2* w2 = (const float2*)win;
        const float inv = 1.0f / 512.0f;
        float* yf = y + f * YPITCH;
        #pragma unroll
        for (int m = 0; m < 8; m++) {
            int n = w + (m << 6);
            float2 wv = __ldg(w2 + n);
            float2 o;
            o.x = Xr[m] * inv * wv.x;
            o.y = Xi[m] * inv * wv.y;
            *(float2*)(yf + 2 * n) = o;        // pos 2n, 2n+1
        }
    }
    __syncthreads();

    // =================== overlap-add from shared ===================
    float* outb = out + (size_t)b * OUT_PER_B;
    const float TW3 = 2.0f / 3.0f;

    // interior-owned: tmax in [t0+3, t0+7], l in [256(t0+3), 256(t0+8))
    #pragma unroll
    for (int s = tid; s < 1280; s += 512) {
        int l   = ((t0 + 3) << 8) + s;
        int fl  = 3 + (s >> 8);            // tmax - t0, 3..7
        int pos = s & 255;
        float acc = y[(fl - 3) * YPITCH + pos + 768]
                  + y[(fl - 2) * YPITCH + pos + 512]
                  + y[(fl - 1) * YPITCH + pos + 256]
                  + y[(fl    ) * YPITCH + pos      ];
        outb[l - PAD] = acc * TW3;
    }

    if (t0 != 0) {
        // bottom stripe: l in [256 t0, 256(t0+3))
        #pragma unroll
        for (int s = tid; s < 768; s += 512) {
            int r = s >> 8;                // tmax - t0: 0,1,2
            float acc = y[s];
            if (r >= 1) acc += y[1 * YPITCH + s - 256];
            if (r >= 2) acc += y[2 * YPITCH + s - 512];
            int l = (t0 << 8) + s;
            atomicAdd(outb + (l - PAD), acc * TW3);
        }
    } else {
        // batch start: l in [384, 768), env varies
        if (tid < 384) {
            int l = PAD + tid;
            int tmax = l >> 8;             // 1 or 2
            float acc = 0.0f, env = 0.0f;
            for (int t = 0; t <= tmax; t++) {
                int pos = l - (t << 8);
                float wv = __ldg(win + pos);
                env = fmaf(wv, wv, env);
                acc += y[t * YPITCH + pos];
            }
            outb[l - PAD] = acc / env;
        }
    }

    if (t0 != 2040) {
        // top stripe: l in [256(t0+8), 256(t0+11))
        #pragma unroll
        for (int s = tid; s < 768; s += 512) {
            int r = s >> 8;                // 0,1,2 ; count = 3 - r
            float acc = y[7 * YPITCH + s + 256];
            if (r <= 1) acc += y[6 * YPITCH + s + 512];
            if (r == 0) acc += y[5 * YPITCH + s + 768];
            int l = ((t0 + 8) << 8) + s;
            atomicAdd(outb + (l - PAD), acc * TW3);
        }
    } else {
        // batch end: l in [524288, 524672)
        if (tid < 384) {
            int l = 524288 + tid;
            int tmin = (l - 768) >> 8;     // 2045..2046
            float acc = 0.0f, env = 0.0f;
            for (int t = tmin; t <= 2047; t++) {
                int pos = l - (t << 8);
                float wv = __ldg(win + pos);
                env = fmaf(wv, wv, env);
                acc += y[(t - 2040) * YPITCH + pos];
            }
            outb[l - PAD] = acc / env;
        }
    }
}

extern "C" void kernel_launch(void* const* d_in, const int* in_sizes, int n_in,
                              void* d_out, int out_size)
{
    const float* spr = (const float*)d_in[0];
    const float* spi = (const float*)d_in[1];
    const float* win = (const float*)d_in[2];
    float* out = (float*)d_out;

    cudaFuncSetAttribute(istft_fused_kernel,
                         cudaFuncAttributeMaxDynamicSharedMemorySize, SM_BYTES);

    istft_zero_kernel<<<8192, 256>>>((float4*)out);
    istft_fused_kernel<<<NFRAMES / FPB, 512, SM_BYTES>>>(spr, spi, win, out);
}